// round 5
// baseline (speedup 1.0000x reference)
#include <cuda_runtime.h>
#include <math.h>

#define B_     1024
#define NI_    64
#define NN_    8256
#define E_     131072
#define NOUT_  64
#define MAXP2  128     // pass-2 edges per output node (expected ~16, max ~36)
#define MAXP1  16      // input edges per node (Poisson mean 0.12, max ~5)
#define MAXROW 48      // inline row-mode sources per output node (expected ~2)
#define TPB    256
#define GRID   128     // <= SM count -> all blocks co-resident -> spin is safe

// -------- scratch (__device__ globals) --------
__device__ int   g_p2_cnt[NOUT_];
__device__ int   g_p2_src[NOUT_ * MAXP2];
__device__ int   g_p2_e  [NOUT_ * MAXP2];
__device__ int   g_p1_cnt[NN_];
__device__ int   g_p1_src[NN_ * MAXP1];
__device__ int   g_p1_e  [NN_ * MAXP1];
__device__ unsigned char g_has_in[NN_];
__device__ __align__(16) float g_inT[NI_ * B_];   // inputs transposed [feature][batch]

// self-resetting grid barrier state (count returns to 0 every barrier;
// generation increments monotonically -> identical work on every replay)
__device__ volatile unsigned g_gen;
__device__ unsigned          g_cnt;

__device__ __forceinline__ void gridbar() {
    __syncthreads();
    if (threadIdx.x == 0) {
        unsigned my = g_gen;
        __threadfence();
        if (atomicAdd(&g_cnt, 1u) == GRID - 1) {
            g_cnt = 0;                 // reset before release (no new arrivals possible)
            __threadfence();
            g_gen = my + 1;            // release
        } else {
            while (g_gen == my) { }    // spin (all blocks resident)
        }
        __threadfence();
    }
    __syncthreads();
}

__device__ __forceinline__ void scan_edge(int e, int d, int s) {
    g_has_in[d] = 1;
    if (d < NOUT_) {                           // pass-2 edge
        int pos = atomicAdd(&g_p2_cnt[d], 1);
        if (pos < MAXP2) {
            g_p2_src[d * MAXP2 + pos] = s;
            g_p2_e  [d * MAXP2 + pos] = e;
        }
    }
    if (s < NI_) {                             // pass-1 contributing edge (state0 == 0)
        int pos = atomicAdd(&g_p1_cnt[d], 1);
        if (pos < MAXP1) {
            g_p1_src[d * MAXP1 + pos] = s;
            g_p1_e  [d * MAXP1 + pos] = e;
        }
    }
}

__global__ void __launch_bounds__(TPB) k_all(const float* __restrict__ in,
                                             const float* __restrict__ w,
                                             const float* __restrict__ bias,
                                             const float* __restrict__ resp,
                                             const int*   __restrict__ src,
                                             const int*   __restrict__ dst,
                                             float*       __restrict__ out) {
    int blk = blockIdx.x, t = threadIdx.x;

    // ---- phase 0: transpose (blocks 0-15) | zero counters (blocks 16-127) ----
    __shared__ float tile[64][65];
    if (blk < 16) {
        int r0 = blk * 64;
        #pragma unroll
        for (int idx = t; idx < 64 * 64; idx += TPB) {
            int r = idx >> 6, c = idx & 63;            // coalesced load (c fast)
            tile[r][c] = in[(r0 + r) * NI_ + c];
        }
        __syncthreads();
        #pragma unroll
        for (int idx = t; idx < 64 * 64; idx += TPB) {
            int c = idx >> 6, r = idx & 63;            // coalesced store (r fast)
            g_inT[c * B_ + r0 + r] = tile[r][c];
        }
    } else {
        int i = (blk - 16) * TPB + t;                  // 112*256 = 28672 >= NN_
        if (i < NN_) { g_p1_cnt[i] = 0; g_has_in[i] = 0; }
        if (i < NOUT_) g_p2_cnt[i] = 0;
    }
    gridbar();

    // ---- phase 1: edge scan, one int4 chunk per thread (128*256 == E_/4) ----
    {
        int tid = blk * TPB + t;
        int4 d4 = ((const int4*)dst)[tid];
        int4 s4 = ((const int4*)src)[tid];
        int e0 = tid * 4;
        scan_edge(e0 + 0, d4.x, s4.x);
        scan_edge(e0 + 1, d4.y, s4.y);
        scan_edge(e0 + 2, d4.z, s4.z);
        scan_edge(e0 + 3, d4.w, s4.w);
    }
    gridbar();

    // ---- phase 2: blocks 0-63 compute output nodes ----
    if (blk >= NOUT_) return;
    int n = blk;
    __shared__ int   s_meta[2];
    __shared__ int   s_nd, s_ni;
    __shared__ float s_const;
    __shared__ const float4* s_dptr[MAXP2];            // direct input-feature sources
    __shared__ float         s_dw  [MAXP2];
    __shared__ float s_iw[MAXROW];                     // inline row-mode sources
    __shared__ float s_ib[MAXROW];
    __shared__ float s_ir[MAXROW];
    __shared__ int   s_ik[MAXROW];
    __shared__ int   s_isrc[MAXROW * MAXP1];
    __shared__ float s_iew [MAXROW * MAXP1];
    if (t == 0) { s_meta[0] = g_has_in[n]; s_meta[1] = g_p2_cnt[n];
                  s_nd = 0; s_ni = 0; s_const = 0.f; }
    __syncthreads();
    int has = s_meta[0];
    int k = s_meta[1]; if (k > MAXP2) k = MAXP2;
    if (has) {
        for (int i = t; i < k; i += TPB) {
            int   s  = g_p2_src[n * MAXP2 + i];
            float wi = w[g_p2_e[n * MAXP2 + i]];
            if (s < NI_) {
                int pos = atomicAdd(&s_nd, 1);
                s_dptr[pos] = (const float4*)(g_inT + (size_t)s * B_);
                s_dw  [pos] = wi;
            } else {
                int j = s - NI_;
                if (g_has_in[j]) {
                    int k1 = g_p1_cnt[j]; if (k1 > MAXP1) k1 = MAXP1;
                    if (k1 == 0) {
                        atomicAdd(&s_const, wi * tanhf(bias[j]));
                    } else {
                        int pos = atomicAdd(&s_ni, 1);
                        if (pos < MAXROW) {
                            s_iw[pos] = wi;
                            s_ib[pos] = bias[j];
                            s_ir[pos] = resp[j];
                            s_ik[pos] = k1;
                            for (int q = 0; q < k1; q++) {
                                s_isrc[pos * MAXP1 + q] = g_p1_src[j * MAXP1 + q];
                                s_iew [pos * MAXP1 + q] = w[g_p1_e[j * MAXP1 + q]];
                            }
                        }
                    }
                }
                // !has_in[j] -> source value is exactly 0, contributes nothing
            }
        }
    }
    __syncthreads();
    int b0 = 4 * t;
    if (!has) {
        out[(b0 + 0) * NOUT_ + n] = 0.f;
        out[(b0 + 1) * NOUT_ + n] = 0.f;
        out[(b0 + 2) * NOUT_ + n] = 0.f;
        out[(b0 + 3) * NOUT_ + n] = 0.f;
        return;
    }
    int   nd = s_nd;
    int   ni = s_ni; if (ni > MAXROW) ni = MAXROW;
    float rn = resp[n];
    float bn = fmaf(rn, s_const, bias[n]);             // const sources folded into bias
    float4 agg = make_float4(0.f, 0.f, 0.f, 0.f);
    for (int i = 0; i < nd; i++) {                     // direct input-feature sources
        float4 v = s_dptr[i][t];
        float wi = s_dw[i];
        agg.x = fmaf(wi, v.x, agg.x);
        agg.y = fmaf(wi, v.y, agg.y);
        agg.z = fmaf(wi, v.z, agg.z);
        agg.w = fmaf(wi, v.w, agg.w);
    }
    for (int i = 0; i < ni; i++) {                     // inline row-mode sources
        int k1 = s_ik[i];
        float4 a = make_float4(0.f, 0.f, 0.f, 0.f);
        for (int q = 0; q < k1; q++) {
            float4 v = ((const float4*)(g_inT + (size_t)s_isrc[i * MAXP1 + q] * B_))[t];
            float wq = s_iew[i * MAXP1 + q];
            a.x = fmaf(wq, v.x, a.x);
            a.y = fmaf(wq, v.y, a.y);
            a.z = fmaf(wq, v.z, a.z);
            a.w = fmaf(wq, v.w, a.w);
        }
        float bj = s_ib[i], rj = s_ir[i], wi = s_iw[i];
        agg.x = fmaf(wi, tanhf(fmaf(rj, a.x, bj)), agg.x);
        agg.y = fmaf(wi, tanhf(fmaf(rj, a.y, bj)), agg.y);
        agg.z = fmaf(wi, tanhf(fmaf(rj, a.z, bj)), agg.z);
        agg.w = fmaf(wi, tanhf(fmaf(rj, a.w, bj)), agg.w);
    }
    out[(b0 + 0) * NOUT_ + n] = tanhf(fmaf(rn, agg.x, bn));
    out[(b0 + 1) * NOUT_ + n] = tanhf(fmaf(rn, agg.y, bn));
    out[(b0 + 2) * NOUT_ + n] = tanhf(fmaf(rn, agg.z, bn));
    out[(b0 + 3) * NOUT_ + n] = tanhf(fmaf(rn, agg.w, bn));
}

// -------- launch: ONE kernel --------
extern "C" void kernel_launch(void* const* d_in, const int* in_sizes, int n_in,
                              void* d_out, int out_size) {
    const float* inputs  = (const float*)d_in[0];
    const float* weights = (const float*)d_in[1];
    const float* bias    = (const float*)d_in[2];
    const float* resp    = (const float*)d_in[3];
    const int*   src     = (const int*)d_in[4];
    const int*   dst     = (const int*)d_in[5];
    float*       out     = (float*)d_out;

    k_all<<<GRID, TPB>>>(inputs, weights, bias, resp, src, dst, out);
}

// round 6
// speedup vs baseline: 1.0472x; 1.0472x over previous
#include <cuda_runtime.h>
#include <math.h>

#define B_     1024
#define NI_    64
#define NN_    8256
#define E_     131072
#define NOUT_  64
#define MAXP2  128     // pass-2 edges per output node (expected ~16, max ~36)
#define MAXP1  16      // input edges per node (Poisson mean 0.12, max ~5)
#define MAXROW 48      // inline row-mode sources per output node (expected ~2)
#define TPB    1024
#define GRID   128     // <= SM count -> all blocks co-resident -> spin is safe

// -------- scratch (__device__ globals) --------
__device__ int   g_p2_cnt[NOUT_];
__device__ int   g_p2_src[NOUT_ * MAXP2];
__device__ int   g_p2_e  [NOUT_ * MAXP2];
__device__ int   g_p1_cnt[NN_];
__device__ int   g_p1_src[NN_ * MAXP1];
__device__ int   g_p1_e  [NN_ * MAXP1];
__device__ unsigned char g_has_in[NN_];
__device__ float g_inT[NI_ * B_];          // inputs transposed [feature][batch]

// self-resetting grid barrier (generation counter -> replay-deterministic)
__device__ volatile unsigned g_gen;
__device__ unsigned          g_cnt;

__device__ __forceinline__ void gridbar() {
    __syncthreads();
    if (threadIdx.x == 0) {
        unsigned my = g_gen;
        __threadfence();
        if (atomicAdd(&g_cnt, 1u) == GRID - 1) {
            g_cnt = 0;                 // reset before release (no new arrivals possible)
            __threadfence();
            g_gen = my + 1;            // release
        } else {
            while (g_gen == my) { }    // spin (all blocks resident)
        }
        __threadfence();
    }
    __syncthreads();
}

__global__ void __launch_bounds__(TPB) k_all(const float* __restrict__ in,
                                             const float* __restrict__ w,
                                             const float* __restrict__ bias,
                                             const float* __restrict__ resp,
                                             const int*   __restrict__ src,
                                             const int*   __restrict__ dst,
                                             float*       __restrict__ out) {
    int blk = blockIdx.x, t = threadIdx.x;

    // ---- phase 0: transpose (blocks 0-15) | zero counters (blocks 16-127) ----
    __shared__ float tile[64][65];
    if (blk < 16) {
        int r0 = blk * 64;
        #pragma unroll
        for (int idx = t; idx < 64 * 64; idx += TPB) {
            int r = idx >> 6, c = idx & 63;            // coalesced load (c fast)
            tile[r][c] = in[(r0 + r) * NI_ + c];
        }
        __syncthreads();
        #pragma unroll
        for (int idx = t; idx < 64 * 64; idx += TPB) {
            int c = idx >> 6, r = idx & 63;            // coalesced store (r fast)
            g_inT[c * B_ + r0 + r] = tile[r][c];
        }
    } else {
        int i = (blk - 16) * TPB + t;                  // 112*1024 >= NN_
        if (i < NN_) { g_p1_cnt[i] = 0; g_has_in[i] = 0; }
        if (i < NOUT_) g_p2_cnt[i] = 0;
    }
    gridbar();

    // ---- phase 1: edge scan, exactly ONE edge per thread (128*1024 == E_) ----
    {
        int e = blk * TPB + t;
        int d = dst[e];
        int s = src[e];
        g_has_in[d] = 1;
        if (d < NOUT_) {                               // pass-2 edge
            int pos = atomicAdd(&g_p2_cnt[d], 1);
            if (pos < MAXP2) {
                g_p2_src[d * MAXP2 + pos] = s;
                g_p2_e  [d * MAXP2 + pos] = e;
            }
        }
        if (s < NI_) {                                 // pass-1 edge (state0 == 0)
            int pos = atomicAdd(&g_p1_cnt[d], 1);
            if (pos < MAXP1) {
                g_p1_src[d * MAXP1 + pos] = s;
                g_p1_e  [d * MAXP1 + pos] = e;
            }
        }
    }
    gridbar();

    // ---- phase 2: block n < 64 computes output node n; thread t = batch t ----
    if (blk >= NOUT_) return;
    int n = blk;
    __shared__ int   s_meta[2];
    __shared__ int   s_nd, s_ni;
    __shared__ float s_const;
    __shared__ int   s_dsrc[MAXP2];                    // direct input-feature sources
    __shared__ float s_dw  [MAXP2];
    __shared__ float s_iw[MAXROW];                     // inline row-mode sources
    __shared__ float s_ib[MAXROW];
    __shared__ float s_ir[MAXROW];
    __shared__ int   s_ik[MAXROW];
    __shared__ int   s_isrc[MAXROW * MAXP1];
    __shared__ float s_iew [MAXROW * MAXP1];
    if (t == 0) { s_meta[0] = g_has_in[n]; s_meta[1] = g_p2_cnt[n];
                  s_nd = 0; s_ni = 0; s_const = 0.f; }
    __syncthreads();
    int has = s_meta[0];
    int k = s_meta[1]; if (k > MAXP2) k = MAXP2;
    if (has && t < k) {
        int   s  = g_p2_src[n * MAXP2 + t];
        float wi = w[g_p2_e[n * MAXP2 + t]];
        if (s < NI_) {
            int pos = atomicAdd(&s_nd, 1);
            s_dsrc[pos] = s;
            s_dw  [pos] = wi;
        } else {
            int j = s - NI_;
            if (g_has_in[j]) {
                int k1 = g_p1_cnt[j]; if (k1 > MAXP1) k1 = MAXP1;
                if (k1 == 0) {
                    atomicAdd(&s_const, wi * tanhf(bias[j]));
                } else {
                    int pos = atomicAdd(&s_ni, 1);
                    if (pos < MAXROW) {
                        s_iw[pos] = wi;
                        s_ib[pos] = bias[j];
                        s_ir[pos] = resp[j];
                        s_ik[pos] = k1;
                        for (int q = 0; q < k1; q++) {
                            s_isrc[pos * MAXP1 + q] = g_p1_src[j * MAXP1 + q];
                            s_iew [pos * MAXP1 + q] = w[g_p1_e[j * MAXP1 + q]];
                        }
                    }
                }
            }
            // !has_in[j] -> source value is exactly 0, contributes nothing
        }
    }
    __syncthreads();
    if (!has) { out[t * NOUT_ + n] = 0.f; return; }
    int   nd = s_nd;
    int   ni = s_ni; if (ni > MAXROW) ni = MAXROW;
    float rn = resp[n];
    float bn = fmaf(rn, s_const, bias[n]);             // const sources folded into bias
    float agg = 0.f;
    for (int i = 0; i < nd; i++)                       // direct input-feature sources
        agg = fmaf(s_dw[i], g_inT[s_dsrc[i] * B_ + t], agg);
    for (int i = 0; i < ni; i++) {                     // inline row-mode sources
        int k1 = s_ik[i];
        float a = 0.f;
        for (int q = 0; q < k1; q++)
            a = fmaf(s_iew[i * MAXP1 + q], g_inT[s_isrc[i * MAXP1 + q] * B_ + t], a);
        agg = fmaf(s_iw[i], tanhf(fmaf(s_ir[i], a, s_ib[i])), agg);
    }
    out[t * NOUT_ + n] = tanhf(fmaf(rn, agg, bn));
}

// -------- launch: ONE kernel --------
extern "C" void kernel_launch(void* const* d_in, const int* in_sizes, int n_in,
                              void* d_out, int out_size) {
    const float* inputs  = (const float*)d_in[0];
    const float* weights = (const float*)d_in[1];
    const float* bias    = (const float*)d_in[2];
    const float* resp    = (const float*)d_in[3];
    const int*   src     = (const int*)d_in[4];
    const int*   dst     = (const int*)d_in[5];
    float*       out     = (float*)d_out;

    k_all<<<GRID, TPB>>>(inputs, weights, bias, resp, src, dst, out);
}

// round 7
// speedup vs baseline: 1.1171x; 1.0668x over previous
#include <cuda_runtime.h>
#include <math.h>

#define B_     1024
#define NI_    64
#define NN_    8256
#define E_     131072
#define NOUT_  64
#define MAXP2  128     // pass-2 edges per output node (expected ~16, max ~36)
#define MAXP1  16      // input edges per node (Poisson mean 0.12, max ~6)
#define MAXROW 48      // inline row-mode sources per output node (expected ~2)

#define PDL_TRIGGER()  asm volatile("griddepcontrol.launch_dependents;" ::: "memory")
#define PDL_WAIT()     asm volatile("griddepcontrol.wait;" ::: "memory")

// -------- scratch (__device__ globals) --------
__device__ int   g_p2_cnt[NOUT_];
__device__ int   g_p2_src[NOUT_ * MAXP2];
__device__ int   g_p2_e  [NOUT_ * MAXP2];
__device__ int   g_p1_cnt[NN_];
__device__ int   g_p1_src[NN_ * MAXP1];
__device__ int   g_p1_e  [NN_ * MAXP1];
__device__ unsigned char g_has_in[NN_];
__device__ float g_inT[NI_ * B_];          // inputs transposed [feature][batch]

// -------- K1: zero counters + coalesced smem transpose (grid 49 x 256) --------
__global__ void __launch_bounds__(256) k_prep(const float* __restrict__ in) {
    PDL_TRIGGER();                                     // let k_scan schedule now
    int blk = blockIdx.x, t = threadIdx.x;
    if (blk < 16) {
        __shared__ float tile[64][65];
        int r0 = blk * 64;
        #pragma unroll
        for (int idx = t; idx < 64 * 64; idx += 256) {
            int r = idx >> 6, c = idx & 63;            // coalesced load (c fast)
            tile[r][c] = in[(r0 + r) * NI_ + c];
        }
        __syncthreads();
        #pragma unroll
        for (int idx = t; idx < 64 * 64; idx += 256) {
            int c = idx >> 6, r = idx & 63;            // coalesced store (r fast)
            g_inT[c * B_ + r0 + r] = tile[r][c];
        }
    } else {
        int i = (blk - 16) * 256 + t;                  // 33*256 = 8448 >= NN_
        if (i < NN_) { g_p1_cnt[i] = 0; g_has_in[i] = 0; }
        if (i < NOUT_) g_p2_cnt[i] = 0;
    }
}

// -------- K2: edge scan, 1 edge/thread (grid 512 x 256), PDL-overlapped --------
__global__ void __launch_bounds__(256) k_scan(const int* __restrict__ src,
                                              const int* __restrict__ dst) {
    PDL_TRIGGER();                                     // let k_out schedule now
    int e = blockIdx.x * 256 + threadIdx.x;
    int d = __ldg(dst + e);                            // pure inputs: load BEFORE wait,
    int s = __ldg(src + e);                            // overlaps k_prep execution
    PDL_WAIT();                                        // counters now zeroed
    g_has_in[d] = 1;
    if (d < NOUT_) {                                   // pass-2 edge
        int pos = atomicAdd(&g_p2_cnt[d], 1);
        if (pos < MAXP2) {
            g_p2_src[d * MAXP2 + pos] = s;
            g_p2_e  [d * MAXP2 + pos] = e;
        }
    }
    if (s < NI_) {                                     // pass-1 edge (state0 == 0)
        int pos = atomicAdd(&g_p1_cnt[d], 1);
        if (pos < MAXP1) {
            g_p1_src[d * MAXP1 + pos] = s;
            g_p1_e  [d * MAXP1 + pos] = e;
        }
    }
}

// -------- K3: output nodes (grid 64 x 1024); thread t = batch t --------
__global__ void __launch_bounds__(1024) k_out(const float* __restrict__ w,
                                              const float* __restrict__ bias,
                                              const float* __restrict__ resp,
                                              float* __restrict__ out) {
    int n = blockIdx.x, t = threadIdx.x;
    __shared__ int   s_meta[2];
    __shared__ int   s_nd, s_ni;
    __shared__ float s_const;
    __shared__ int   s_dsrc[MAXP2];                    // direct input-feature sources
    __shared__ float s_dw  [MAXP2];
    __shared__ float s_iw[MAXROW];                     // inline row-mode sources
    __shared__ float s_ib[MAXROW];
    __shared__ float s_ir[MAXROW];
    __shared__ int   s_ik[MAXROW];
    __shared__ int   s_isrc[MAXROW * MAXP1];
    __shared__ float s_iew [MAXROW * MAXP1];
    if (t == 0) { s_nd = 0; s_ni = 0; s_const = 0.f; } // pre-wait smem init
    float rn = __ldg(resp + n);                        // pure inputs, pre-wait
    float bias_n = __ldg(bias + n);
    PDL_WAIT();                                        // scan results now visible
    if (t == 0) { s_meta[0] = g_has_in[n]; s_meta[1] = g_p2_cnt[n]; }
    __syncthreads();
    int has = s_meta[0];
    int k = s_meta[1]; if (k > MAXP2) k = MAXP2;
    if (has && t < k) {
        int   s  = g_p2_src[n * MAXP2 + t];
        float wi = w[g_p2_e[n * MAXP2 + t]];
        if (s < NI_) {
            int pos = atomicAdd(&s_nd, 1);
            s_dsrc[pos] = s;
            s_dw  [pos] = wi;
        } else {
            int j = s - NI_;
            if (g_has_in[j]) {
                int k1 = g_p1_cnt[j]; if (k1 > MAXP1) k1 = MAXP1;
                if (k1 == 0) {
                    atomicAdd(&s_const, wi * tanhf(bias[j]));
                } else {
                    int pos = atomicAdd(&s_ni, 1);
                    if (pos < MAXROW) {
                        s_iw[pos] = wi;
                        s_ib[pos] = bias[j];
                        s_ir[pos] = resp[j];
                        s_ik[pos] = k1;
                        for (int q = 0; q < k1; q++) {
                            s_isrc[pos * MAXP1 + q] = g_p1_src[j * MAXP1 + q];
                            s_iew [pos * MAXP1 + q] = w[g_p1_e[j * MAXP1 + q]];
                        }
                    }
                }
            }
            // !has_in[j] -> source value is exactly 0, contributes nothing
        }
    }
    __syncthreads();
    if (!has) { out[t * NOUT_ + n] = 0.f; return; }
    int   nd = s_nd;
    int   ni = s_ni; if (ni > MAXROW) ni = MAXROW;
    float bn = fmaf(rn, s_const, bias_n);              // const sources folded into bias
    float agg = 0.f;
    for (int i = 0; i < nd; i++)                       // direct input-feature sources
        agg = fmaf(s_dw[i], g_inT[s_dsrc[i] * B_ + t], agg);
    for (int i = 0; i < ni; i++) {                     // inline row-mode sources
        int k1 = s_ik[i];
        float a = 0.f;
        for (int q = 0; q < k1; q++)
            a = fmaf(s_iew[i * MAXP1 + q], g_inT[s_isrc[i * MAXP1 + q] * B_ + t], a);
        agg = fmaf(s_iw[i], tanhf(fmaf(s_ir[i], a, s_ib[i])), agg);
    }
    out[t * NOUT_ + n] = tanhf(fmaf(rn, agg, bn));
}

// -------- launch: 3 kernels chained with PDL --------
extern "C" void kernel_launch(void* const* d_in, const int* in_sizes, int n_in,
                              void* d_out, int out_size) {
    const float* inputs  = (const float*)d_in[0];
    const float* weights = (const float*)d_in[1];
    const float* bias    = (const float*)d_in[2];
    const float* resp    = (const float*)d_in[3];
    const int*   src     = (const int*)d_in[4];
    const int*   dst     = (const int*)d_in[5];
    float*       out     = (float*)d_out;

    k_prep<<<49, 256>>>(inputs);

    cudaLaunchAttribute at[1];
    at[0].id = cudaLaunchAttributeProgrammaticStreamSerialization;
    at[0].val.programmaticStreamSerializationAllowed = 1;

    cudaLaunchConfig_t cfg{};
    cfg.attrs = at; cfg.numAttrs = 1; cfg.stream = 0;

    cfg.gridDim = dim3(512); cfg.blockDim = dim3(256);
    cudaLaunchKernelEx(&cfg, k_scan, src, dst);

    cfg.gridDim = dim3(NOUT_); cfg.blockDim = dim3(1024);
    cudaLaunchKernelEx(&cfg, k_out, weights, bias, resp, out);
}